// round 11
// baseline (speedup 1.0000x reference)
#include <cuda_runtime.h>
#include <cuda_bf16.h>
#include <cstdint>

// YOLOv3 decode: x [16, 255, 76, 76] fp32 -> out [16, 3*5776, 85] fp32
// R11 = R10 (LDG.64 lanes, tanh-sigmoid, conflict-light STS, TMA bulk store)
// with 2x coarser tiles: YTPB=512, HWT=128, 4 CTAs/SM (same 2048 thr/SM,
// same 32-reg budget). Halves per-tile boundary overhead (barriers, TMA
// issue, wait_group drain events), which is the residual DRAM-idle source
// (R10: DRAM 62.9%, issue 26.7%, nothing saturated).

#define YHW    5776
#define YC     85
#define HWT    128
#define YTPB   512
#define CHUNKS 46                  // 45 full + tail of 16 hw
#define NTILES (48 * CHUNKS)       // 2208
#define NBLK   592                 // 148 x 4

__device__ __forceinline__ float ytanh(float x) {
    float r;
    asm("tanh.approx.f32 %0, %1;" : "=f"(r) : "f"(x));
    return r;
}
__device__ __forceinline__ float ysig(float v) {
    return fmaf(0.5f, ytanh(0.5f * v), 0.5f);     // 1 MUFU + 1 FMA
}

template <bool TAIL>
__device__ __forceinline__ void load_tile(
    const float* __restrict__ xs, float* __restrict__ smb,
    int hw0, int nhw, float aw, float ah, int wid, int lane)
{
    // 44 warp-units: g = 0..41 -> (channel quad g>>1, hw-half g&1),
    //                g = 42,43 -> (c==84, hw-half g&1). 64 hw per unit.
    #pragma unroll 3
    for (int g = wid; g < 44; g += 16) {
        const int half = g & 1;
        const int hwe  = half * 64 + 2 * lane;     // even hw within tile
        if (TAIL && hwe >= nhw) continue;
        if (g < 42) {
            const int c0 = (g >> 1) * 4;
            const float2* p = (const float2*)(xs + (size_t)c0 * YHW) + half * 32 + lane;
            float2 va = p[0];                      // channel c0
            float2 vb = p[YHW / 2];                // c0+1
            float2 vc = p[YHW];                    // c0+2
            float2 vd = p[3 * (YHW / 2)];          // c0+3
            if ((g >> 1) == 0) {
                const unsigned hw = (unsigned)(hw0 + hwe);      // even
                const unsigned hh = (hw * 55189u) >> 22;        // hw / 76
                const unsigned ww = hw - hh * 76u;              // even -> pair no wrap
                const float fw = (float)ww, fh = (float)hh;
                va.x = (ysig(va.x) + fw)        * (1.0f / 76.0f);
                va.y = (ysig(va.y) + fw + 1.0f) * (1.0f / 76.0f);
                vb.x = (ysig(vb.x) + fh)        * (1.0f / 76.0f);
                vb.y = (ysig(vb.y) + fh)        * (1.0f / 76.0f);
                vc.x = __expf(vc.x) * aw;  vc.y = __expf(vc.y) * aw;
                vd.x = __expf(vd.x) * ah;  vd.y = __expf(vd.y) * ah;
            } else {
                va.x = ysig(va.x); va.y = ysig(va.y);
                vb.x = ysig(vb.x); vb.y = ysig(vb.y);
                vc.x = ysig(vc.x); vc.y = ysig(vc.y);
                vd.x = ysig(vd.x); vd.y = ysig(vd.y);
            }
            float* d = smb + (size_t)hwe * YC + c0;
            // even-hw row: element index even -> 8B-aligned STS.64
            *(float2*)(d)     = make_float2(va.x, vb.x);
            *(float2*)(d + 2) = make_float2(vc.x, vd.x);
            // odd-hw row: scalar stores
            d[YC]     = va.y;
            d[YC + 1] = vb.y;
            d[YC + 2] = vc.y;
            d[YC + 3] = vd.y;
        } else {
            const float2* p = (const float2*)(xs + (size_t)84 * YHW) + half * 32 + lane;
            float2 v = p[0];
            float* d = smb + (size_t)hwe * YC + 84;
            d[0]  = ysig(v.x);
            d[YC] = ysig(v.y);
        }
    }
}

__global__ __launch_bounds__(YTPB, 4) void Yolo_59966333387037_kernel(
    const float* __restrict__ x,
    const float* __restrict__ anchors,
    float* __restrict__ out)
{
    __shared__ __align__(16) float sm[HWT * YC];   // 43520 B, single buffer

    const int wid  = threadIdx.x >> 5;
    const int lane = threadIdx.x & 31;

    bool first = true;
    for (int tile = blockIdx.x; tile < NTILES; tile += NBLK) {
        const int s     = tile / CHUNKS;
        const int chunk = tile - s * CHUNKS;
        const int a     = s % 3;
        const float aw  = __ldg(anchors + 2 * a)     * (1.0f / 608.0f);
        const float ah  = __ldg(anchors + 2 * a + 1) * (1.0f / 608.0f);
        const int hw0   = chunk * HWT;
        const int nhw   = min(HWT, YHW - hw0);      // 128 or 16
        const float* xs = x + (size_t)s * YC * YHW + hw0;

        // Previous TMA store must have finished READING smem before overwrite.
        if (!first) {
            if (threadIdx.x == 0)
                asm volatile("cp.async.bulk.wait_group.read 0;" ::: "memory");
            __syncthreads();
        }
        first = false;

        if (nhw == HWT) load_tile<false>(xs, sm, hw0, nhw, aw, ah, wid, lane);
        else            load_tile<true >(xs, sm, hw0, nhw, aw, ah, wid, lane);
        __syncthreads();

        if (threadIdx.x == 0) {
            asm volatile("fence.proxy.async.shared::cta;" ::: "memory");
            uint32_t saddr;
            asm("{ .reg .u64 t; cvta.to.shared.u64 t, %1; cvt.u32.u64 %0, t; }"
                : "=r"(saddr) : "l"((const void*)sm));
            float* dst = out + ((size_t)s * YHW + hw0) * YC;
            const int bytes = nhw * YC * 4;         // 43520 or 5440
            asm volatile(
                "cp.async.bulk.global.shared::cta.bulk_group [%0], [%1], %2;"
                :: "l"(dst), "r"(saddr), "r"(bytes) : "memory");
            asm volatile("cp.async.bulk.commit_group;" ::: "memory");
        }
    }

    if (threadIdx.x == 0)
        asm volatile("cp.async.bulk.wait_group 0;" ::: "memory");
}

extern "C" void kernel_launch(void* const* d_in, const int* in_sizes, int n_in,
                              void* d_out, int out_size)
{
    const float* x       = (const float*)d_in[0];
    const float* anchors = (const float*)d_in[1];
    float* out           = (float*)d_out;

    Yolo_59966333387037_kernel<<<NBLK, YTPB>>>(x, anchors, out);
}